// round 12
// baseline (speedup 1.0000x reference)
#include <cuda_runtime.h>
#include <cuda_bf16.h>
#include <cstdint>

// DiffPool: B=8, N=2048, F=C=K=128.
// out: X_pooled[8,128,128] | A_pooled[8,128,128] | S[8,2048,128] | LP_loss | entr_loss
//
// A exactly binary -> exact bf16; HMMA mma.sync m16n8k16 fp32-acc.
//   P1: logits = d*(A@Yp + Yp) -> fused softmax -> S fp32, Shi/Slo, dShi, entropy
//   P2: A@[Shi | dShi] (128x256 CTA tile) -> Thi/Tlo, U=d*acc+d^2*S -> Uhi/Ulo
//   K5T (hi/lo, hh+hl+lh): X_pooled = U^T Xe, A_pooled = S^T T, G = S^T S
//   LP^2_b = sumA_b - 2 tr(A_pooled_b) + ||G_b||_F^2
// 64x64 warp tiles (4.0 mma/ldsm), K-chunk 64, 2-stage pipeline.
// R11 bug fixed: A-tile rows are 128 B/chunk = 8 x 16B transfers (was 4 -> NaN).

#define BB 8
#define NN 2048
#define ROWS (BB*NN)
#define OUT_AP 131072
#define OUT_S  262144
#define OUT_LP 2359296
#define OUT_ENT 2359297

// P1 buffer: A 128x64bf16 (stride 144B) = 18432 + B 64x128 (swz 256B) = 16384 -> 34816
#define P1BUF 34816
#define P1SMEM (2*P1BUF)
// P2 buffer: A 18432 + S 16384 + dS 16384 = 51200
#define P2BUF 51200
#define P2SMEM (2*P2BUF)
// K5T buffer: 4 arrays x (32 x 256B) = 32768; 3 buffers
#define K5BUF 32768
#define K5SMEM (3*K5BUF)

// ---- scratch ----
__device__ __nv_bfloat16 g_Abf[(size_t)ROWS*2048];
__device__ float g_Yp[(size_t)ROWS*128];
__device__ __nv_bfloat16 g_Yphi[(size_t)ROWS*128];
__device__ __nv_bfloat16 g_Xehi[(size_t)ROWS*128];
__device__ __nv_bfloat16 g_Xelo[(size_t)ROWS*128];
__device__ __nv_bfloat16 g_Shi[(size_t)ROWS*128];
__device__ __nv_bfloat16 g_Slo[(size_t)ROWS*128];
__device__ __nv_bfloat16 g_dShi[(size_t)ROWS*128];
__device__ __nv_bfloat16 g_Thi[(size_t)ROWS*128];
__device__ __nv_bfloat16 g_Tlo[(size_t)ROWS*128];
__device__ __nv_bfloat16 g_Uhi[(size_t)ROWS*128];
__device__ __nv_bfloat16 g_Ulo[(size_t)ROWS*128];
__device__ float g_d[ROWS];
__device__ int   g_nnz[ROWS];
__device__ float g_entrRow[ROWS];
__device__ float g_part[(size_t)3*8*8*16384];
__device__ float g_G[8*128*128];

// ---------------- PTX helpers ----------------
__device__ __forceinline__ uint32_t smem_u32(const void* p) {
    uint32_t a;
    asm("{ .reg .u64 t; cvta.to.shared.u64 t, %1; cvt.u32.u64 %0, t; }" : "=r"(a) : "l"(p));
    return a;
}
__device__ __forceinline__ void cpa16(uint32_t s, const void* g) {
    asm volatile("cp.async.cg.shared.global [%0], [%1], 16;" :: "r"(s), "l"(g));
}
#define CPA_COMMIT() asm volatile("cp.async.commit_group;" ::: "memory")
#define CPA_WAIT1()  asm volatile("cp.async.wait_group 1;" ::: "memory")
#define CPA_WAIT0()  asm volatile("cp.async.wait_group 0;" ::: "memory")

__device__ __forceinline__ void ldsm4(uint32_t& r0, uint32_t& r1, uint32_t& r2, uint32_t& r3,
                                      uint32_t a) {
    asm volatile("ldmatrix.sync.aligned.m8n8.x4.shared.b16 {%0,%1,%2,%3}, [%4];"
                 : "=r"(r0), "=r"(r1), "=r"(r2), "=r"(r3) : "r"(a));
}
__device__ __forceinline__ void ldsm4t(uint32_t& r0, uint32_t& r1, uint32_t& r2, uint32_t& r3,
                                       uint32_t a) {
    asm volatile("ldmatrix.sync.aligned.m8n8.x4.trans.shared.b16 {%0,%1,%2,%3}, [%4];"
                 : "=r"(r0), "=r"(r1), "=r"(r2), "=r"(r3) : "r"(a));
}
__device__ __forceinline__ void mma_bf16(float4& d, const uint32_t* a, const uint32_t* b) {
    asm volatile("mma.sync.aligned.m16n8k16.row.col.f32.bf16.bf16.f32 "
                 "{%0,%1,%2,%3}, {%4,%5,%6,%7}, {%8,%9}, {%0,%1,%2,%3};"
                 : "+f"(d.x), "+f"(d.y), "+f"(d.z), "+f"(d.w)
                 : "r"(a[0]), "r"(a[1]), "r"(a[2]), "r"(a[3]), "r"(b[0]), "r"(b[1]));
}

// =====================================================================
// K1: row-sum of A + exact bf16 conversion
// =====================================================================
__global__ void k1_scan(const float* __restrict__ A) {
    int row = blockIdx.x;
    int t = threadIdx.x;
    const float4* ar = reinterpret_cast<const float4*>(A + (size_t)row * NN);
    __nv_bfloat16* dstb = g_Abf + (size_t)row * NN;
    int cnt = 0;
    #pragma unroll
    for (int i = 0; i < 2; i++) {
        int cg = t + (i << 8);
        float4 v = ar[cg];
        cnt += (v.x != 0.f) + (v.y != 0.f) + (v.z != 0.f) + (v.w != 0.f);
        __nv_bfloat162 p0 = __floats2bfloat162_rn(v.x, v.y);
        __nv_bfloat162 p1 = __floats2bfloat162_rn(v.z, v.w);
        *reinterpret_cast<__nv_bfloat162*>(dstb + (cg << 2))     = p0;
        *reinterpret_cast<__nv_bfloat162*>(dstb + (cg << 2) + 2) = p1;
    }
    int lane = t & 31, w = t >> 5;
    #pragma unroll
    for (int o = 16; o > 0; o >>= 1) cnt += __shfl_xor_sync(0xffffffffu, cnt, o);
    __shared__ int wtot[8];
    if (lane == 0) wtot[w] = cnt;
    __syncthreads();
    if (t == 0) {
        int s = 0;
        #pragma unroll
        for (int i = 0; i < 8; i++) s += wtot[i];
        g_nnz[row] = s;
        g_d[row] = rsqrtf((float)s + 1.0f);
    }
}

// =====================================================================
// K2: Xe = X@W_emb -> hi/lo bf16; Yp = d*(X@W_pool) fp32 + bf16 hi
// =====================================================================
__global__ void k2_xw(const float* __restrict__ X, const float* __restrict__ We,
                      const float* __restrict__ Wp) {
    __shared__ float shW[32][256];
    __shared__ float shX[32][32];
    int t = threadIdx.x;
    int tx = t & 31, ty = t >> 5;
    int row0 = blockIdx.x * 32;
    float acc[4][8];
    #pragma unroll
    for (int i = 0; i < 4; i++)
        #pragma unroll
        for (int j = 0; j < 8; j++) acc[i][j] = 0.f;

    for (int kb = 0; kb < 4; kb++) {
        __syncthreads();
        #pragma unroll
        for (int r = 0; r < 32; r++) {
            int k = kb * 32 + r;
            shW[r][t] = (t < 128) ? We[k * 128 + t] : Wp[k * 128 + (t - 128)];
        }
        #pragma unroll
        for (int r = 0; r < 4; r++) {
            int li = t + (r << 8);
            int rr = li >> 5, kk = li & 31;
            shX[rr][kk] = X[(size_t)(row0 + rr) * 128 + kb * 32 + kk];
        }
        __syncthreads();
        #pragma unroll
        for (int kk = 0; kk < 32; kk++) {
            float x0 = shX[ty][kk], x1 = shX[ty + 8][kk];
            float x2 = shX[ty + 16][kk], x3 = shX[ty + 24][kk];
            float wv[8];
            #pragma unroll
            for (int j = 0; j < 8; j++) wv[j] = shW[kk][tx * 8 + j];
            #pragma unroll
            for (int j = 0; j < 8; j++) {
                acc[0][j] += x0 * wv[j];
                acc[1][j] += x1 * wv[j];
                acc[2][j] += x2 * wv[j];
                acc[3][j] += x3 * wv[j];
            }
        }
    }
    #pragma unroll
    for (int r = 0; r < 4; r++) {
        int row = row0 + ty + r * 8;
        float dv = g_d[row];
        #pragma unroll
        for (int jj = 0; jj < 2; jj++) {
            if (tx < 16) {
                int cc = tx * 8 + jj * 4;
                #pragma unroll
                for (int q = 0; q < 4; q++) {
                    float v = acc[r][jj * 4 + q];
                    __nv_bfloat16 h = __float2bfloat16_rn(v);
                    g_Xehi[(size_t)row * 128 + cc + q] = h;
                    g_Xelo[(size_t)row * 128 + cc + q] =
                        __float2bfloat16_rn(v - __bfloat162float(h));
                }
            } else {
                int cc = (tx - 16) * 8 + jj * 4;
                float4 v;
                v.x = dv * acc[r][jj * 4 + 0]; v.y = dv * acc[r][jj * 4 + 1];
                v.z = dv * acc[r][jj * 4 + 2]; v.w = dv * acc[r][jj * 4 + 3];
                *reinterpret_cast<float4*>(g_Yp + (size_t)row * 128 + cc) = v;
                __nv_bfloat162 h0 = __floats2bfloat162_rn(v.x, v.y);
                __nv_bfloat162 h1 = __floats2bfloat162_rn(v.z, v.w);
                *reinterpret_cast<__nv_bfloat162*>(g_Yphi + (size_t)row * 128 + cc)     = h0;
                *reinterpret_cast<__nv_bfloat162*>(g_Yphi + (size_t)row * 128 + cc + 2) = h1;
            }
        }
    }
}

// =====================================================================
// P1: 128x128 tile of A@Yphi, fused softmax. grid (16,8), 128 thr
// (4 warps, 2x2 of 64x64 warp tiles), K-chunk 64, 2-stage, 2 CTAs/SM.
// =====================================================================
__global__ void __launch_bounds__(128, 2)
p1_logits(float* __restrict__ out) {
    extern __shared__ char smem[];
    uint32_t sb = smem_u32(smem);
    int tid = threadIdx.x;
    int wid = tid >> 5, lane = tid & 31;
    int n0 = blockIdx.x * 128, b = blockIdx.y;
    const __nv_bfloat16* Ag = g_Abf + ((size_t)b * 2048 + n0) * 2048;
    const __nv_bfloat16* Bg = g_Yphi + (size_t)b * 2048 * 128;

    float4 acc[4][8];
    #pragma unroll
    for (int i = 0; i < 4; i++)
        #pragma unroll
        for (int j = 0; j < 8; j++) acc[i][j] = make_float4(0.f, 0.f, 0.f, 0.f);

    int wr = wid >> 1, wc = wid & 1;               // 2x2 warp grid
    int n0w = wr * 64, c0w = wc * 64;
    int sel = lane >> 3, rr = lane & 7;

    auto stage = [&](int ch, int buf) {
        uint32_t s0 = sb + buf * P1BUF;
        int kc = ch * 64;
        #pragma unroll
        for (int q = 0; q < 8; q++) {              // A: 128 rows x 128B (8x16B), stride 144
            int idx = tid + q * 128;               // 0..1023
            int row = idx >> 3, u = idx & 7;
            cpa16(s0 + row * 144 + u * 16, Ag + (size_t)row * 2048 + kc + u * 8);
        }
        #pragma unroll
        for (int q = 0; q < 8; q++) {              // B: 64 rows x 256B swizzled
            int idx = tid + q * 128;               // 0..1023
            int k = idx >> 4, u = idx & 15;
            uint32_t so = k * 256 + ((u * 16) ^ ((k & 7) << 4));
            cpa16(s0 + 18432 + so, Bg + (size_t)(kc + k) * 128 + u * 8);
        }
        CPA_COMMIT();
    };

    stage(0, 0);
    for (int ch = 0; ch < 32; ch++) {
        if (ch < 31) { stage(ch + 1, (ch + 1) & 1); CPA_WAIT1(); }
        else CPA_WAIT0();
        __syncthreads();
        uint32_t s0 = sb + (ch & 1) * P1BUF;
        #pragma unroll
        for (int ks = 0; ks < 4; ks++) {
            uint32_t a[4][4];
            #pragma unroll
            for (int i = 0; i < 4; i++) {
                int row = n0w + i * 16 + (sel & 1) * 8 + rr;
                ldsm4(a[i][0], a[i][1], a[i][2], a[i][3],
                      s0 + row * 144 + ks * 32 + (sel >> 1) * 16);
            }
            uint32_t bh[8][2];
            #pragma unroll
            for (int cg = 0; cg < 4; cg++) {
                int krow = ks * 16 + (sel & 1) * 8 + rr;
                int colb = (c0w + cg * 16) * 2 + (sel >> 1) * 16;
                uint32_t ad = s0 + 18432 + krow * 256 + (colb ^ ((krow & 7) << 4));
                ldsm4t(bh[cg*2][0], bh[cg*2][1], bh[cg*2+1][0], bh[cg*2+1][1], ad);
            }
            #pragma unroll
            for (int i = 0; i < 4; i++)
                #pragma unroll
                for (int cj = 0; cj < 8; cj++)
                    mma_bf16(acc[i][cj], a[i], bh[cj]);
        }
        __syncthreads();
    }
    CPA_WAIT0();
    __syncthreads();

    float* smlog = reinterpret_cast<float*>(smem);    // [128][132] = 67584B
    int rq = lane >> 2, cq = (lane & 3) * 2;
    #pragma unroll
    for (int i = 0; i < 4; i++)
        #pragma unroll
        for (int cj = 0; cj < 8; cj++) {
            int rowl = n0w + i * 16 + rq;
            int col = c0w + cj * 8 + cq;
            *reinterpret_cast<float2*>(&smlog[rowl * 132 + col])       = make_float2(acc[i][cj].x, acc[i][cj].y);
            *reinterpret_cast<float2*>(&smlog[(rowl + 8) * 132 + col]) = make_float2(acc[i][cj].z, acc[i][cj].w);
        }
    __syncthreads();

    for (int r = 0; r < 32; r++) {
        int rowl = wid * 32 + r;
        size_t nr = (size_t)b * 2048 + n0 + rowl;
        float dn = g_d[nr];
        float4 Lc = *reinterpret_cast<float4*>(&smlog[rowl * 132 + lane * 4]);
        float4 Yv = reinterpret_cast<const float4*>(g_Yp + nr * 128)[lane];
        float l0 = dn * (Lc.x + Yv.x), l1 = dn * (Lc.y + Yv.y);
        float l2 = dn * (Lc.z + Yv.z), l3 = dn * (Lc.w + Yv.w);
        float m = fmaxf(fmaxf(l0, l1), fmaxf(l2, l3));
        #pragma unroll
        for (int o = 16; o > 0; o >>= 1) m = fmaxf(m, __shfl_xor_sync(0xffffffffu, m, o));
        float e0 = expf(l0 - m), e1 = expf(l1 - m), e2 = expf(l2 - m), e3 = expf(l3 - m);
        float ss = (e0 + e1) + (e2 + e3);
        #pragma unroll
        for (int o = 16; o > 0; o >>= 1) ss += __shfl_xor_sync(0xffffffffu, ss, o);
        float inv = 1.f / ss;
        float s0v = e0 * inv, s1v = e1 * inv, s2v = e2 * inv, s3v = e3 * inv;
        reinterpret_cast<float4*>(out + OUT_S + nr * 128)[lane] = make_float4(s0v, s1v, s2v, s3v);
        float sv[4] = {s0v, s1v, s2v, s3v};
        #pragma unroll
        for (int q = 0; q < 4; q++) {
            __nv_bfloat16 h = __float2bfloat16_rn(sv[q]);
            g_Shi[nr * 128 + lane * 4 + q] = h;
            g_Slo[nr * 128 + lane * 4 + q] = __float2bfloat16_rn(sv[q] - __bfloat162float(h));
        }
        __nv_bfloat162 dh0 = __floats2bfloat162_rn(dn * s0v, dn * s1v);
        __nv_bfloat162 dh1 = __floats2bfloat162_rn(dn * s2v, dn * s3v);
        *reinterpret_cast<__nv_bfloat162*>(g_dShi + nr * 128 + lane * 4)     = dh0;
        *reinterpret_cast<__nv_bfloat162*>(g_dShi + nr * 128 + lane * 4 + 2) = dh1;
        float ent = -(s0v * logf(s0v + 1e-7f) + s1v * logf(s1v + 1e-7f)
                    + s2v * logf(s2v + 1e-7f) + s3v * logf(s3v + 1e-7f));
        #pragma unroll
        for (int o = 16; o > 0; o >>= 1) ent += __shfl_xor_sync(0xffffffffu, ent, o);
        if (lane == 0) g_entrRow[nr] = ent;
    }
}

// =====================================================================
// P2: 128x256 tile of A@[Shi | dShi] -> Thi/Tlo, Uhi/Ulo.
// grid (16,8), 256 thr (8 warps, 2x4 of 64x64), K-chunk 64, 2-stage.
// =====================================================================
__global__ void __launch_bounds__(256, 1)
p2_TU(const float* __restrict__ out) {
    extern __shared__ char smem[];
    uint32_t sb = smem_u32(smem);
    int tid = threadIdx.x;
    int wid = tid >> 5, lane = tid & 31;
    int n0 = blockIdx.x * 128, b = blockIdx.y;
    const __nv_bfloat16* Ag = g_Abf + ((size_t)b * 2048 + n0) * 2048;
    const __nv_bfloat16* Sg = g_Shi + (size_t)b * 2048 * 128;
    const __nv_bfloat16* Dg = g_dShi + (size_t)b * 2048 * 128;

    float4 acc[4][8];
    #pragma unroll
    for (int i = 0; i < 4; i++)
        #pragma unroll
        for (int j = 0; j < 8; j++) acc[i][j] = make_float4(0.f, 0.f, 0.f, 0.f);

    int wr = wid >> 2, wc = wid & 3;               // 2x4 warp grid
    int n0w = wr * 64;
    int half = wc >> 1;                            // 0 = S->T, 1 = dS->U
    int c0l = (wc & 1) * 64;                       // col offset within the half
    uint32_t bbase_off = 18432 + (half ? 16384u : 0u);
    int sel = lane >> 3, rr = lane & 7;

    auto stage = [&](int ch, int buf) {
        uint32_t s0 = sb + buf * P2BUF;
        int kc = ch * 64;
        #pragma unroll
        for (int q = 0; q < 4; q++) {              // A: 128 rows x 128B (8x16B), stride 144
            int idx = tid + q * 256;               // 0..1023
            int row = idx >> 3, u = idx & 7;
            cpa16(s0 + row * 144 + u * 16, Ag + (size_t)row * 2048 + kc + u * 8);
        }
        #pragma unroll
        for (int q = 0; q < 8; q++) {              // S and dS: 64 x 256B each
            int idx = tid + q * 256;               // 0..2047
            int blk = idx >> 10, r = idx & 1023;
            int k = r >> 4, u = r & 15;
            uint32_t so = k * 256 + ((u * 16) ^ ((k & 7) << 4));
            const __nv_bfloat16* src = blk ? Dg : Sg;
            cpa16(s0 + 18432 + blk * 16384 + so, src + (size_t)(kc + k) * 128 + u * 8);
        }
        CPA_COMMIT();
    };

    stage(0, 0);
    for (int ch = 0; ch < 32; ch++) {
        if (ch < 31) { stage(ch + 1, (ch + 1) & 1); CPA_WAIT1(); }
        else CPA_WAIT0();
        __syncthreads();
        uint32_t s0 = sb + (ch & 1) * P2BUF;
        #pragma unroll
        for (int ks = 0; ks < 4; ks++) {
            uint32_t a[4][4];
            #pragma unroll
            for (int i = 0; i < 4; i++) {
                int row = n0w + i * 16 + (sel & 1) * 8 + rr;
                ldsm4(a[i][0], a[i][1], a[i][2], a[i][3],
                      s0 + row * 144 + ks * 32 + (sel >> 1) * 16);
            }
            uint32_t bh[8][2];
            #pragma unroll
            for (int cg = 0; cg < 4; cg++) {
                int krow = ks * 16 + (sel & 1) * 8 + rr;
                int colb = (c0l + cg * 16) * 2 + (sel >> 1) * 16;
                uint32_t ad = s0 + bbase_off + krow * 256 + (colb ^ ((krow & 7) << 4));
                ldsm4t(bh[cg*2][0], bh[cg*2][1], bh[cg*2+1][0], bh[cg*2+1][1], ad);
            }
            #pragma unroll
            for (int i = 0; i < 4; i++)
                #pragma unroll
                for (int cj = 0; cj < 8; cj++)
                    mma_bf16(acc[i][cj], a[i], bh[cj]);
        }
        __syncthreads();
    }
    CPA_WAIT0();

    int rq = lane >> 2, cq = (lane & 3) * 2;
    __nv_bfloat16* Hd = half ? g_Uhi : g_Thi;
    __nv_bfloat16* Ld = half ? g_Ulo : g_Tlo;
    #pragma unroll
    for (int i = 0; i < 4; i++)
        #pragma unroll
        for (int cj = 0; cj < 8; cj++) {
            int n = n0 + n0w + i * 16 + rq;
            int c = c0l + cj * 8 + cq;
            size_t nr0 = (size_t)b * 2048 + n;
            size_t nr1 = nr0 + 8;
            float v0x = acc[i][cj].x, v0y = acc[i][cj].y;
            float v1x = acc[i][cj].z, v1y = acc[i][cj].w;
            if (half) {
                float d0 = g_d[nr0], d1 = g_d[nr1];
                float2 sv0 = *reinterpret_cast<const float2*>(&out[OUT_S + nr0 * 128 + c]);
                float2 sv1 = *reinterpret_cast<const float2*>(&out[OUT_S + nr1 * 128 + c]);
                v0x = d0 * v0x + d0 * d0 * sv0.x;
                v0y = d0 * v0y + d0 * d0 * sv0.y;
                v1x = d1 * v1x + d1 * d1 * sv1.x;
                v1y = d1 * v1y + d1 * d1 * sv1.y;
            }
            __nv_bfloat16 h;
            h = __float2bfloat16_rn(v0x); Hd[nr0*128+c]   = h; Ld[nr0*128+c]   = __float2bfloat16_rn(v0x - __bfloat162float(h));
            h = __float2bfloat16_rn(v0y); Hd[nr0*128+c+1] = h; Ld[nr0*128+c+1] = __float2bfloat16_rn(v0y - __bfloat162float(h));
            h = __float2bfloat16_rn(v1x); Hd[nr1*128+c]   = h; Ld[nr1*128+c]   = __float2bfloat16_rn(v1x - __bfloat162float(h));
            h = __float2bfloat16_rn(v1y); Hd[nr1*128+c+1] = h; Ld[nr1*128+c+1] = __float2bfloat16_rn(v1y - __bfloat162float(h));
        }
}

// =====================================================================
// K5T: tensorized L^T R, hi/lo (hh+hl+lh). Split-K over n; 3 bufs,
// 2 in flight, drain-aware tail. grid (8,8,3), 256 thr.
// =====================================================================
__global__ void __launch_bounds__(256, 2)
k5t_outer() {
    extern __shared__ char smem[];
    uint32_t sb = smem_u32(smem);
    int tid = threadIdx.x;
    int wid = tid >> 5, lane = tid & 31;
    int split = blockIdx.x, b = blockIdx.y, p = blockIdx.z;
    size_t boff = (size_t)b * 2048 * 128;

    const __nv_bfloat16* src[4];
    if (p == 0)      { src[0] = g_Uhi; src[1] = g_Ulo; src[2] = g_Xehi; src[3] = g_Xelo; }
    else if (p == 1) { src[0] = g_Shi; src[1] = g_Slo; src[2] = g_Thi;  src[3] = g_Tlo; }
    else             { src[0] = g_Shi; src[1] = g_Slo; src[2] = g_Shi;  src[3] = g_Slo; }

    float4 acc[2][8];
    #pragma unroll
    for (int i = 0; i < 2; i++)
        #pragma unroll
        for (int j = 0; j < 8; j++) acc[i][j] = make_float4(0.f, 0.f, 0.f, 0.f);

    int c1w = (wid >> 1) * 32, c2w = (wid & 1) * 64;
    int sel = lane >> 3, rr = lane & 7;

    auto stage = [&](int ch) {
        uint32_t s0 = sb + (ch % 3) * K5BUF;
        int nc = split * 256 + ch * 32;
        #pragma unroll
        for (int q = 0; q < 8; q++) {
            int arr = q >> 1;
            int r = ((q & 1) << 8) + tid;
            int k = r >> 4, u = r & 15;
            uint32_t so = k * 256 + ((u * 16) ^ ((k & 7) << 4));
            cpa16(s0 + arr * 8192 + so, src[arr] + boff + (size_t)(nc + k) * 128 + u * 8);
        }
        CPA_COMMIT();
    };

    stage(0); stage(1);
    for (int ch = 0; ch < 8; ch++) {
        if (ch < 7) CPA_WAIT1();
        else CPA_WAIT0();
        __syncthreads();
        uint32_t s0 = sb + (ch % 3) * K5BUF;
        #pragma unroll
        for (int ks = 0; ks < 2; ks++) {
            uint32_t lh[2][4], ll[2][4];
            #pragma unroll
            for (int i = 0; i < 2; i++) {
                int krow = ks * 16 + (sel >> 1) * 8 + rr;
                int colb = (c1w + i * 16 + (sel & 1) * 8) * 2;
                uint32_t ad = krow * 256 + (colb ^ ((krow & 7) << 4));
                ldsm4t(lh[i][0], lh[i][1], lh[i][2], lh[i][3], s0 + ad);
                ldsm4t(ll[i][0], ll[i][1], ll[i][2], ll[i][3], s0 + 8192 + ad);
            }
            #pragma unroll
            for (int cg = 0; cg < 4; cg++) {
                int krow = ks * 16 + (sel & 1) * 8 + rr;
                int colb = (c2w + cg * 16) * 2 + (sel >> 1) * 16;
                uint32_t ad = krow * 256 + (colb ^ ((krow & 7) << 4));
                uint32_t rh[2][2], rl[2][2];
                ldsm4t(rh[0][0], rh[0][1], rh[1][0], rh[1][1], s0 + 16384 + ad);
                ldsm4t(rl[0][0], rl[0][1], rl[1][0], rl[1][1], s0 + 24576 + ad);
                #pragma unroll
                for (int i = 0; i < 2; i++)
                    #pragma unroll
                    for (int h = 0; h < 2; h++) {
                        int cj = cg * 2 + h;
                        mma_bf16(acc[i][cj], lh[i], rh[h]);
                        mma_bf16(acc[i][cj], lh[i], rl[h]);
                        mma_bf16(acc[i][cj], ll[i], rh[h]);
                    }
            }
        }
        if (ch + 2 < 8) stage(ch + 2);
    }
    CPA_WAIT0();

    float* dst = g_part + ((size_t)((p * 8 + b) * 8 + split)) * 16384;
    int rq = lane >> 2, cq = (lane & 3) * 2;
    #pragma unroll
    for (int i = 0; i < 2; i++)
        #pragma unroll
        for (int cj = 0; cj < 8; cj++) {
            int c1 = c1w + i * 16 + rq;
            int c2 = c2w + cj * 8 + cq;
            *reinterpret_cast<float2*>(&dst[c1 * 128 + c2])       = make_float2(acc[i][cj].x, acc[i][cj].y);
            *reinterpret_cast<float2*>(&dst[(c1 + 8) * 128 + c2]) = make_float2(acc[i][cj].z, acc[i][cj].w);
        }
}

// =====================================================================
// K5b: reduce 8 split-K partials -> X_pooled, A_pooled (out), G
// =====================================================================
__global__ void k5b_reduce(float* __restrict__ out) {
    int idx = blockIdx.x * blockDim.x + threadIdx.x;
    if (idx >= 3 * 8 * 16384) return;
    int p = idx / 131072;
    int rem = idx - p * 131072;
    int b = rem >> 14;
    int kc = rem & 16383;
    const float* s0 = g_part + ((size_t)(p * 8 + b) * 8) * 16384 + kc;
    float s = 0.f;
    #pragma unroll
    for (int ch = 0; ch < 8; ch++) s += s0[(size_t)ch * 16384];
    if (p == 0)      out[(size_t)b * 16384 + kc] = s;
    else if (p == 1) out[OUT_AP + (size_t)b * 16384 + kc] = s;
    else             g_G[b * 16384 + kc] = s;
}

// =====================================================================
// K6: losses. LP_b^2 = sumA_b - 2 tr(A_pooled_b) + ||G_b||_F^2
// =====================================================================
__global__ void k6_final(float* __restrict__ out) {
    int t = threadIdx.x;
    __shared__ float red[256];

    float lo = 0.f;
    for (int i = t; i < ROWS; i += 256) lo += g_entrRow[i];
    red[t] = lo; __syncthreads();
    for (int s2 = 128; s2 > 0; s2 >>= 1) {
        if (t < s2) red[t] += red[t + s2];
        __syncthreads();
    }
    float entr = red[0] / (float)ROWS;
    __syncthreads();

    float lpsum = 0.f;
    for (int b = 0; b < 8; b++) {
        float la = 0.f;
        for (int i = t; i < NN; i += 256) la += (float)g_nnz[b * NN + i];
        red[t] = la; __syncthreads();
        for (int s2 = 128; s2 > 0; s2 >>= 1) { if (t < s2) red[t] += red[t + s2]; __syncthreads(); }
        float sumA = red[0]; __syncthreads();

        float ltr = (t < 128) ? out[OUT_AP + (size_t)b * 16384 + t * 129] : 0.f;
        red[t] = ltr; __syncthreads();
        for (int s2 = 128; s2 > 0; s2 >>= 1) { if (t < s2) red[t] += red[t + s2]; __syncthreads(); }
        float tr = red[0]; __syncthreads();

        float lg = 0.f;
        for (int i = t; i < 16384; i += 256) { float v = g_G[b * 16384 + i]; lg += v * v; }
        red[t] = lg; __syncthreads();
        for (int s2 = 128; s2 > 0; s2 >>= 1) { if (t < s2) red[t] += red[t + s2]; __syncthreads(); }
        float gg = red[0]; __syncthreads();

        lpsum += sqrtf(fmaxf(sumA - 2.f * tr + gg, 0.f));
    }
    if (t == 0) {
        out[OUT_LP] = lpsum / 8.0f;
        out[OUT_ENT] = entr;
    }
}

// =====================================================================
extern "C" void kernel_launch(void* const* d_in, const int* in_sizes, int n_in,
                              void* d_out, int out_size) {
    const float* X  = (const float*)d_in[0];
    const float* A  = (const float*)d_in[1];
    const float* We = (const float*)d_in[2];
    const float* Wp = (const float*)d_in[3];
    float* out = (float*)d_out;

    cudaFuncSetAttribute(p1_logits, cudaFuncAttributeMaxDynamicSharedMemorySize, P1SMEM);
    cudaFuncSetAttribute(p2_TU, cudaFuncAttributeMaxDynamicSharedMemorySize, P2SMEM);
    cudaFuncSetAttribute(k5t_outer, cudaFuncAttributeMaxDynamicSharedMemorySize, K5SMEM);

    k1_scan<<<ROWS, 256>>>(A);
    k2_xw<<<ROWS / 32, 256>>>(X, We, Wp);
    dim3 gd(16, 8);
    p1_logits<<<gd, 128, P1SMEM>>>(out);
    p2_TU<<<gd, 256, P2SMEM>>>(out);
    dim3 g5(8, 8, 3);
    k5t_outer<<<g5, 256, K5SMEM>>>();
    k5b_reduce<<<(3 * 8 * 16384 + 255) / 256, 256>>>(out);
    k6_final<<<1, 256>>>(out);
}

// round 13
// speedup vs baseline: 1.1600x; 1.1600x over previous
#include <cuda_runtime.h>
#include <cuda_bf16.h>
#include <cstdint>

// DiffPool: B=8, N=2048, F=C=K=128.
// out: X_pooled[8,128,128] | A_pooled[8,128,128] | S[8,2048,128] | LP_loss | entr_loss
//
// A exactly binary -> exact bf16; HMMA mma.sync m16n8k16 fp32-acc.
//   P1: logits = d*(A@Yp + Yp) -> fused softmax -> S fp32, Shi/Slo, dShi, entropy
//   P2: A@[Shi | dShi] (64x256 tile) -> Thi/Tlo, U=d*acc+d^2*S -> Uhi/Ulo
//   K5T (hi/lo, hh+hl+lh): X_pooled = U^T Xe, A_pooled = S^T T, G = S^T S
//   LP^2_b = sumA_b - 2 tr(A_pooled_b) + ||G_b||_F^2
// Mainloops: proven R6/R7 shape (K-chunk 64, 2-stage, 32x64 warp tiles).
// This round: hi/lo epilogue stores vectorized to __nv_bfloat162 (the R6->R7
// 12.6us regression was scattered 2B stores); k5t keeps drain-aware tail.

#define BB 8
#define NN 2048
#define ROWS (BB*NN)
#define OUT_AP 131072
#define OUT_S  262144
#define OUT_LP 2359296
#define OUT_ENT 2359297

// P1 buffer: A 64x64bf16 (stride 144B) = 9216 + B 64x128 (swz 256B) = 16384 -> 25600
#define P1BUF 25600
#define P1SMEM (2*P1BUF)
// P2 buffer: A 9216 + S 16384 + dS 16384 = 41984
#define P2BUF 41984
#define P2SMEM (2*P2BUF)
// K5T buffer: 4 arrays x (32 x 256B) = 32768; 3 buffers
#define K5BUF 32768
#define K5SMEM (3*K5BUF)

// ---- scratch ----
__device__ __nv_bfloat16 g_Abf[(size_t)ROWS*2048];
__device__ float g_Yp[(size_t)ROWS*128];
__device__ __nv_bfloat16 g_Yphi[(size_t)ROWS*128];
__device__ __nv_bfloat16 g_Xehi[(size_t)ROWS*128];
__device__ __nv_bfloat16 g_Xelo[(size_t)ROWS*128];
__device__ __nv_bfloat16 g_Shi[(size_t)ROWS*128];
__device__ __nv_bfloat16 g_Slo[(size_t)ROWS*128];
__device__ __nv_bfloat16 g_dShi[(size_t)ROWS*128];
__device__ __nv_bfloat16 g_Thi[(size_t)ROWS*128];
__device__ __nv_bfloat16 g_Tlo[(size_t)ROWS*128];
__device__ __nv_bfloat16 g_Uhi[(size_t)ROWS*128];
__device__ __nv_bfloat16 g_Ulo[(size_t)ROWS*128];
__device__ float g_d[ROWS];
__device__ int   g_nnz[ROWS];
__device__ float g_entrRow[ROWS];
__device__ float g_part[(size_t)3*8*8*16384];
__device__ float g_G[8*128*128];

// ---------------- PTX helpers ----------------
__device__ __forceinline__ uint32_t smem_u32(const void* p) {
    uint32_t a;
    asm("{ .reg .u64 t; cvta.to.shared.u64 t, %1; cvt.u32.u64 %0, t; }" : "=r"(a) : "l"(p));
    return a;
}
__device__ __forceinline__ void cpa16(uint32_t s, const void* g) {
    asm volatile("cp.async.cg.shared.global [%0], [%1], 16;" :: "r"(s), "l"(g));
}
#define CPA_COMMIT() asm volatile("cp.async.commit_group;" ::: "memory")
#define CPA_WAIT1()  asm volatile("cp.async.wait_group 1;" ::: "memory")
#define CPA_WAIT0()  asm volatile("cp.async.wait_group 0;" ::: "memory")

__device__ __forceinline__ void ldsm4(uint32_t& r0, uint32_t& r1, uint32_t& r2, uint32_t& r3,
                                      uint32_t a) {
    asm volatile("ldmatrix.sync.aligned.m8n8.x4.shared.b16 {%0,%1,%2,%3}, [%4];"
                 : "=r"(r0), "=r"(r1), "=r"(r2), "=r"(r3) : "r"(a));
}
__device__ __forceinline__ void ldsm4t(uint32_t& r0, uint32_t& r1, uint32_t& r2, uint32_t& r3,
                                       uint32_t a) {
    asm volatile("ldmatrix.sync.aligned.m8n8.x4.trans.shared.b16 {%0,%1,%2,%3}, [%4];"
                 : "=r"(r0), "=r"(r1), "=r"(r2), "=r"(r3) : "r"(a));
}
__device__ __forceinline__ void mma_bf16(float4& d, const uint32_t* a, const uint32_t* b) {
    asm volatile("mma.sync.aligned.m16n8k16.row.col.f32.bf16.bf16.f32 "
                 "{%0,%1,%2,%3}, {%4,%5,%6,%7}, {%8,%9}, {%0,%1,%2,%3};"
                 : "+f"(d.x), "+f"(d.y), "+f"(d.z), "+f"(d.w)
                 : "r"(a[0]), "r"(a[1]), "r"(a[2]), "r"(a[3]), "r"(b[0]), "r"(b[1]));
}
__device__ __forceinline__ void store_hilo2(__nv_bfloat16* Hd, __nv_bfloat16* Ld,
                                            size_t base, float vx, float vy) {
    __nv_bfloat16 h0 = __float2bfloat16_rn(vx);
    __nv_bfloat16 h1 = __float2bfloat16_rn(vy);
    __nv_bfloat16 l0 = __float2bfloat16_rn(vx - __bfloat162float(h0));
    __nv_bfloat16 l1 = __float2bfloat16_rn(vy - __bfloat162float(h1));
    *reinterpret_cast<__nv_bfloat162*>(Hd + base) = __halves2bfloat162(h0, h1);
    *reinterpret_cast<__nv_bfloat162*>(Ld + base) = __halves2bfloat162(l0, l1);
}

// =====================================================================
// K1: row-sum of A + exact bf16 conversion
// =====================================================================
__global__ void k1_scan(const float* __restrict__ A) {
    int row = blockIdx.x;
    int t = threadIdx.x;
    const float4* ar = reinterpret_cast<const float4*>(A + (size_t)row * NN);
    __nv_bfloat16* dstb = g_Abf + (size_t)row * NN;
    int cnt = 0;
    #pragma unroll
    for (int i = 0; i < 2; i++) {
        int cg = t + (i << 8);
        float4 v = ar[cg];
        cnt += (v.x != 0.f) + (v.y != 0.f) + (v.z != 0.f) + (v.w != 0.f);
        __nv_bfloat162 p0 = __floats2bfloat162_rn(v.x, v.y);
        __nv_bfloat162 p1 = __floats2bfloat162_rn(v.z, v.w);
        *reinterpret_cast<__nv_bfloat162*>(dstb + (cg << 2))     = p0;
        *reinterpret_cast<__nv_bfloat162*>(dstb + (cg << 2) + 2) = p1;
    }
    int lane = t & 31, w = t >> 5;
    #pragma unroll
    for (int o = 16; o > 0; o >>= 1) cnt += __shfl_xor_sync(0xffffffffu, cnt, o);
    __shared__ int wtot[8];
    if (lane == 0) wtot[w] = cnt;
    __syncthreads();
    if (t == 0) {
        int s = 0;
        #pragma unroll
        for (int i = 0; i < 8; i++) s += wtot[i];
        g_nnz[row] = s;
        g_d[row] = rsqrtf((float)s + 1.0f);
    }
}

// =====================================================================
// K2: Xe = X@W_emb -> hi/lo bf16; Yp = d*(X@W_pool) fp32 + bf16 hi
// =====================================================================
__global__ void k2_xw(const float* __restrict__ X, const float* __restrict__ We,
                      const float* __restrict__ Wp) {
    __shared__ float shW[32][256];
    __shared__ float shX[32][32];
    int t = threadIdx.x;
    int tx = t & 31, ty = t >> 5;
    int row0 = blockIdx.x * 32;
    float acc[4][8];
    #pragma unroll
    for (int i = 0; i < 4; i++)
        #pragma unroll
        for (int j = 0; j < 8; j++) acc[i][j] = 0.f;

    for (int kb = 0; kb < 4; kb++) {
        __syncthreads();
        #pragma unroll
        for (int r = 0; r < 32; r++) {
            int k = kb * 32 + r;
            shW[r][t] = (t < 128) ? We[k * 128 + t] : Wp[k * 128 + (t - 128)];
        }
        #pragma unroll
        for (int r = 0; r < 4; r++) {
            int li = t + (r << 8);
            int rr = li >> 5, kk = li & 31;
            shX[rr][kk] = X[(size_t)(row0 + rr) * 128 + kb * 32 + kk];
        }
        __syncthreads();
        #pragma unroll
        for (int kk = 0; kk < 32; kk++) {
            float x0 = shX[ty][kk], x1 = shX[ty + 8][kk];
            float x2 = shX[ty + 16][kk], x3 = shX[ty + 24][kk];
            float wv[8];
            #pragma unroll
            for (int j = 0; j < 8; j++) wv[j] = shW[kk][tx * 8 + j];
            #pragma unroll
            for (int j = 0; j < 8; j++) {
                acc[0][j] += x0 * wv[j];
                acc[1][j] += x1 * wv[j];
                acc[2][j] += x2 * wv[j];
                acc[3][j] += x3 * wv[j];
            }
        }
    }
    #pragma unroll
    for (int r = 0; r < 4; r++) {
        int row = row0 + ty + r * 8;
        float dv = g_d[row];
        #pragma unroll
        for (int jj = 0; jj < 2; jj++) {
            if (tx < 16) {
                int cc = tx * 8 + jj * 4;
                store_hilo2(g_Xehi, g_Xelo, (size_t)row * 128 + cc,
                            acc[r][jj * 4 + 0], acc[r][jj * 4 + 1]);
                store_hilo2(g_Xehi, g_Xelo, (size_t)row * 128 + cc + 2,
                            acc[r][jj * 4 + 2], acc[r][jj * 4 + 3]);
            } else {
                int cc = (tx - 16) * 8 + jj * 4;
                float4 v;
                v.x = dv * acc[r][jj * 4 + 0]; v.y = dv * acc[r][jj * 4 + 1];
                v.z = dv * acc[r][jj * 4 + 2]; v.w = dv * acc[r][jj * 4 + 3];
                *reinterpret_cast<float4*>(g_Yp + (size_t)row * 128 + cc) = v;
                __nv_bfloat162 h0 = __floats2bfloat162_rn(v.x, v.y);
                __nv_bfloat162 h1 = __floats2bfloat162_rn(v.z, v.w);
                *reinterpret_cast<__nv_bfloat162*>(g_Yphi + (size_t)row * 128 + cc)     = h0;
                *reinterpret_cast<__nv_bfloat162*>(g_Yphi + (size_t)row * 128 + cc + 2) = h1;
            }
        }
    }
}

// =====================================================================
// P1: 64x128 tile of A@Yphi, fused softmax. grid (32,8), 256 thr,
// K-chunk 64, 2-stage, (256,2).
// =====================================================================
__global__ void __launch_bounds__(256, 2)
p1_logits(float* __restrict__ out) {
    extern __shared__ char smem[];
    uint32_t sb = smem_u32(smem);
    int tid = threadIdx.x;
    int wid = tid >> 5, lane = tid & 31;
    int n0 = blockIdx.x * 64, b = blockIdx.y;
    const __nv_bfloat16* Ag = g_Abf + ((size_t)b * 2048 + n0) * 2048;
    const __nv_bfloat16* Bg = g_Yphi + (size_t)b * 2048 * 128;

    float4 acc[2][4];
    #pragma unroll
    for (int i = 0; i < 2; i++)
        #pragma unroll
        for (int j = 0; j < 4; j++) acc[i][j] = make_float4(0.f, 0.f, 0.f, 0.f);

    int n0w = (wid >> 2) * 32, c0w = (wid & 3) * 32;
    int sel = lane >> 3, rr = lane & 7;

    auto stage = [&](int ch, int buf) {
        uint32_t s0 = sb + buf * P1BUF;
        int kc = ch * 64;
        #pragma unroll
        for (int q = 0; q < 2; q++) {
            int idx = tid + q * 256;
            int row = idx >> 3, u = idx & 7;
            cpa16(s0 + row * 144 + u * 16, Ag + (size_t)row * 2048 + kc + u * 8);
        }
        #pragma unroll
        for (int q = 0; q < 4; q++) {
            int idx = tid + q * 256;
            int k = idx >> 4, u = idx & 15;
            uint32_t so = k * 256 + ((u * 16) ^ ((k & 7) << 4));
            cpa16(s0 + 9216 + so, Bg + (size_t)(kc + k) * 128 + u * 8);
        }
        CPA_COMMIT();
    };

    stage(0, 0);
    for (int ch = 0; ch < 32; ch++) {
        if (ch < 31) { stage(ch + 1, (ch + 1) & 1); CPA_WAIT1(); }
        else CPA_WAIT0();
        __syncthreads();
        uint32_t s0 = sb + (ch & 1) * P1BUF;
        #pragma unroll
        for (int ks = 0; ks < 4; ks++) {
            uint32_t a[2][4];
            #pragma unroll
            for (int i = 0; i < 2; i++) {
                int row = n0w + i * 16 + (sel & 1) * 8 + rr;
                ldsm4(a[i][0], a[i][1], a[i][2], a[i][3],
                      s0 + row * 144 + ks * 32 + (sel >> 1) * 16);
            }
            uint32_t bh[4][2];
            #pragma unroll
            for (int cg = 0; cg < 2; cg++) {
                int krow = ks * 16 + (sel & 1) * 8 + rr;
                int colb = (c0w + cg * 16) * 2 + (sel >> 1) * 16;
                uint32_t ad = s0 + 9216 + krow * 256 + (colb ^ ((krow & 7) << 4));
                ldsm4t(bh[cg*2][0], bh[cg*2][1], bh[cg*2+1][0], bh[cg*2+1][1], ad);
            }
            #pragma unroll
            for (int i = 0; i < 2; i++)
                #pragma unroll
                for (int cj = 0; cj < 4; cj++)
                    mma_bf16(acc[i][cj], a[i], bh[cj]);
        }
        __syncthreads();
    }
    CPA_WAIT0();
    __syncthreads();

    float* smlog = reinterpret_cast<float*>(smem);    // [64][132] = 33792B
    int rq = lane >> 2, cq = (lane & 3) * 2;
    #pragma unroll
    for (int i = 0; i < 2; i++)
        #pragma unroll
        for (int cj = 0; cj < 4; cj++) {
            int rowl = n0w + i * 16 + rq;
            int col = c0w + cj * 8 + cq;
            *reinterpret_cast<float2*>(&smlog[rowl * 132 + col])       = make_float2(acc[i][cj].x, acc[i][cj].y);
            *reinterpret_cast<float2*>(&smlog[(rowl + 8) * 132 + col]) = make_float2(acc[i][cj].z, acc[i][cj].w);
        }
    __syncthreads();

    #pragma unroll
    for (int r = 0; r < 8; r++) {
        int rowl = wid * 8 + r;
        size_t nr = (size_t)b * 2048 + n0 + rowl;
        float dn = g_d[nr];
        float4 Lc = *reinterpret_cast<float4*>(&smlog[rowl * 132 + lane * 4]);
        float4 Yv = reinterpret_cast<const float4*>(g_Yp + nr * 128)[lane];
        float l0 = dn * (Lc.x + Yv.x), l1 = dn * (Lc.y + Yv.y);
        float l2 = dn * (Lc.z + Yv.z), l3 = dn * (Lc.w + Yv.w);
        float m = fmaxf(fmaxf(l0, l1), fmaxf(l2, l3));
        #pragma unroll
        for (int o = 16; o > 0; o >>= 1) m = fmaxf(m, __shfl_xor_sync(0xffffffffu, m, o));
        float e0 = expf(l0 - m), e1 = expf(l1 - m), e2 = expf(l2 - m), e3 = expf(l3 - m);
        float ss = (e0 + e1) + (e2 + e3);
        #pragma unroll
        for (int o = 16; o > 0; o >>= 1) ss += __shfl_xor_sync(0xffffffffu, ss, o);
        float inv = 1.f / ss;
        float s0v = e0 * inv, s1v = e1 * inv, s2v = e2 * inv, s3v = e3 * inv;
        reinterpret_cast<float4*>(out + OUT_S + nr * 128)[lane] = make_float4(s0v, s1v, s2v, s3v);
        store_hilo2(g_Shi, g_Slo, nr * 128 + lane * 4,     s0v, s1v);
        store_hilo2(g_Shi, g_Slo, nr * 128 + lane * 4 + 2, s2v, s3v);
        __nv_bfloat162 dh0 = __floats2bfloat162_rn(dn * s0v, dn * s1v);
        __nv_bfloat162 dh1 = __floats2bfloat162_rn(dn * s2v, dn * s3v);
        *reinterpret_cast<__nv_bfloat162*>(g_dShi + nr * 128 + lane * 4)     = dh0;
        *reinterpret_cast<__nv_bfloat162*>(g_dShi + nr * 128 + lane * 4 + 2) = dh1;
        float ent = -(s0v * logf(s0v + 1e-7f) + s1v * logf(s1v + 1e-7f)
                    + s2v * logf(s2v + 1e-7f) + s3v * logf(s3v + 1e-7f));
        #pragma unroll
        for (int o = 16; o > 0; o >>= 1) ent += __shfl_xor_sync(0xffffffffu, ent, o);
        if (lane == 0) g_entrRow[nr] = ent;
    }
}

// =====================================================================
// P2: 64x256 tile of A@[Shi | dShi] -> Thi/Tlo, Uhi/Ulo (vectorized).
// grid (32,8), 256 thr, K-chunk 64, 2-stage, (256,2).
// =====================================================================
__global__ void __launch_bounds__(256, 2)
p2_TU(const float* __restrict__ out) {
    extern __shared__ char smem[];
    uint32_t sb = smem_u32(smem);
    int tid = threadIdx.x;
    int wid = tid >> 5, lane = tid & 31;
    int n0 = blockIdx.x * 64, b = blockIdx.y;
    const __nv_bfloat16* Ag = g_Abf + ((size_t)b * 2048 + n0) * 2048;
    const __nv_bfloat16* Sg = g_Shi + (size_t)b * 2048 * 128;
    const __nv_bfloat16* Dg = g_dShi + (size_t)b * 2048 * 128;

    float4 acc[2][8];
    #pragma unroll
    for (int i = 0; i < 2; i++)
        #pragma unroll
        for (int j = 0; j < 8; j++) acc[i][j] = make_float4(0.f, 0.f, 0.f, 0.f);

    int n0w = (wid >> 2) * 32;
    int cw = wid & 3;
    int c0l = (cw & 1) * 64;
    uint32_t bbase_off = 9216 + (cw >= 2 ? 16384u : 0u);
    int sel = lane >> 3, rr = lane & 7;

    auto stage = [&](int ch, int buf) {
        uint32_t s0 = sb + buf * P2BUF;
        int kc = ch * 64;
        #pragma unroll
        for (int q = 0; q < 2; q++) {
            int idx = tid + q * 256;
            int row = idx >> 3, u = idx & 7;
            cpa16(s0 + row * 144 + u * 16, Ag + (size_t)row * 2048 + kc + u * 8);
        }
        #pragma unroll
        for (int q = 0; q < 8; q++) {
            int idx = tid + q * 256;
            int blk = idx >> 10, r = idx & 1023;
            int k = r >> 4, u = r & 15;
            uint32_t so = k * 256 + ((u * 16) ^ ((k & 7) << 4));
            const __nv_bfloat16* src = blk ? Dg : Sg;
            cpa16(s0 + 9216 + blk * 16384 + so, src + (size_t)(kc + k) * 128 + u * 8);
        }
        CPA_COMMIT();
    };

    stage(0, 0);
    for (int ch = 0; ch < 32; ch++) {
        if (ch < 31) { stage(ch + 1, (ch + 1) & 1); CPA_WAIT1(); }
        else CPA_WAIT0();
        __syncthreads();
        uint32_t s0 = sb + (ch & 1) * P2BUF;
        #pragma unroll
        for (int ks = 0; ks < 4; ks++) {
            uint32_t a[2][4];
            #pragma unroll
            for (int i = 0; i < 2; i++) {
                int row = n0w + i * 16 + (sel & 1) * 8 + rr;
                ldsm4(a[i][0], a[i][1], a[i][2], a[i][3],
                      s0 + row * 144 + ks * 32 + (sel >> 1) * 16);
            }
            uint32_t bh[8][2];
            #pragma unroll
            for (int cg = 0; cg < 4; cg++) {
                int krow = ks * 16 + (sel & 1) * 8 + rr;
                int colb = (c0l + cg * 16) * 2 + (sel >> 1) * 16;
                uint32_t ad = s0 + bbase_off + krow * 256 + (colb ^ ((krow & 7) << 4));
                ldsm4t(bh[cg*2][0], bh[cg*2][1], bh[cg*2+1][0], bh[cg*2+1][1], ad);
            }
            #pragma unroll
            for (int i = 0; i < 2; i++)
                #pragma unroll
                for (int cj = 0; cj < 8; cj++)
                    mma_bf16(acc[i][cj], a[i], bh[cj]);
        }
        __syncthreads();
    }
    CPA_WAIT0();

    int rq = lane >> 2, cq = (lane & 3) * 2;
    bool isU = (cw >= 2);
    __nv_bfloat16* Hd = isU ? g_Uhi : g_Thi;
    __nv_bfloat16* Ld = isU ? g_Ulo : g_Tlo;
    #pragma unroll
    for (int i = 0; i < 2; i++)
        #pragma unroll
        for (int cj = 0; cj < 8; cj++) {
            int n = n0 + n0w + i * 16 + rq;
            int c = c0l + cj * 8 + cq;
            size_t nr0 = (size_t)b * 2048 + n;
            size_t nr1 = nr0 + 8;
            float v0x = acc[i][cj].x, v0y = acc[i][cj].y;
            float v1x = acc[i][cj].z, v1y = acc[i][cj].w;
            if (isU) {
                float d0 = g_d[nr0], d1 = g_d[nr1];
                float2 sv0 = *reinterpret_cast<const float2*>(&out[OUT_S + nr0 * 128 + c]);
                float2 sv1 = *reinterpret_cast<const float2*>(&out[OUT_S + nr1 * 128 + c]);
                v0x = d0 * v0x + d0 * d0 * sv0.x;
                v0y = d0 * v0y + d0 * d0 * sv0.y;
                v1x = d1 * v1x + d1 * d1 * sv1.x;
                v1y = d1 * v1y + d1 * d1 * sv1.y;
            }
            store_hilo2(Hd, Ld, nr0 * 128 + c, v0x, v0y);
            store_hilo2(Hd, Ld, nr1 * 128 + c, v1x, v1y);
        }
}

// =====================================================================
// K5T: tensorized L^T R, hi/lo (hh+hl+lh). Split-K over n; 3 bufs,
// 2 in flight, drain-aware tail. grid (8,8,3), 256 thr.
// =====================================================================
__global__ void __launch_bounds__(256, 2)
k5t_outer() {
    extern __shared__ char smem[];
    uint32_t sb = smem_u32(smem);
    int tid = threadIdx.x;
    int wid = tid >> 5, lane = tid & 31;
    int split = blockIdx.x, b = blockIdx.y, p = blockIdx.z;
    size_t boff = (size_t)b * 2048 * 128;

    const __nv_bfloat16* src[4];
    if (p == 0)      { src[0] = g_Uhi; src[1] = g_Ulo; src[2] = g_Xehi; src[3] = g_Xelo; }
    else if (p == 1) { src[0] = g_Shi; src[1] = g_Slo; src[2] = g_Thi;  src[3] = g_Tlo; }
    else             { src[0] = g_Shi; src[1] = g_Slo; src[2] = g_Shi;  src[3] = g_Slo; }

    float4 acc[2][8];
    #pragma unroll
    for (int i = 0; i < 2; i++)
        #pragma unroll
        for (int j = 0; j < 8; j++) acc[i][j] = make_float4(0.f, 0.f, 0.f, 0.f);

    int c1w = (wid >> 1) * 32, c2w = (wid & 1) * 64;
    int sel = lane >> 3, rr = lane & 7;

    auto stage = [&](int ch) {
        uint32_t s0 = sb + (ch % 3) * K5BUF;
        int nc = split * 256 + ch * 32;
        #pragma unroll
        for (int q = 0; q < 8; q++) {
            int arr = q >> 1;
            int r = ((q & 1) << 8) + tid;
            int k = r >> 4, u = r & 15;
            uint32_t so = k * 256 + ((u * 16) ^ ((k & 7) << 4));
            cpa16(s0 + arr * 8192 + so, src[arr] + boff + (size_t)(nc + k) * 128 + u * 8);
        }
        CPA_COMMIT();
    };

    stage(0); stage(1);
    for (int ch = 0; ch < 8; ch++) {
        if (ch < 7) CPA_WAIT1();
        else CPA_WAIT0();
        __syncthreads();
        uint32_t s0 = sb + (ch % 3) * K5BUF;
        #pragma unroll
        for (int ks = 0; ks < 2; ks++) {
            uint32_t lh[2][4], ll[2][4];
            #pragma unroll
            for (int i = 0; i < 2; i++) {
                int krow = ks * 16 + (sel >> 1) * 8 + rr;
                int colb = (c1w + i * 16 + (sel & 1) * 8) * 2;
                uint32_t ad = krow * 256 + (colb ^ ((krow & 7) << 4));
                ldsm4t(lh[i][0], lh[i][1], lh[i][2], lh[i][3], s0 + ad);
                ldsm4t(ll[i][0], ll[i][1], ll[i][2], ll[i][3], s0 + 8192 + ad);
            }
            #pragma unroll
            for (int cg = 0; cg < 4; cg++) {
                int krow = ks * 16 + (sel & 1) * 8 + rr;
                int colb = (c2w + cg * 16) * 2 + (sel >> 1) * 16;
                uint32_t ad = krow * 256 + (colb ^ ((krow & 7) << 4));
                uint32_t rh[2][2], rl[2][2];
                ldsm4t(rh[0][0], rh[0][1], rh[1][0], rh[1][1], s0 + 16384 + ad);
                ldsm4t(rl[0][0], rl[0][1], rl[1][0], rl[1][1], s0 + 24576 + ad);
                #pragma unroll
                for (int i = 0; i < 2; i++)
                    #pragma unroll
                    for (int h = 0; h < 2; h++) {
                        int cj = cg * 2 + h;
                        mma_bf16(acc[i][cj], lh[i], rh[h]);
                        mma_bf16(acc[i][cj], lh[i], rl[h]);
                        mma_bf16(acc[i][cj], ll[i], rh[h]);
                    }
            }
        }
        if (ch + 2 < 8) stage(ch + 2);
    }
    CPA_WAIT0();

    float* dst = g_part + ((size_t)((p * 8 + b) * 8 + split)) * 16384;
    int rq = lane >> 2, cq = (lane & 3) * 2;
    #pragma unroll
    for (int i = 0; i < 2; i++)
        #pragma unroll
        for (int cj = 0; cj < 8; cj++) {
            int c1 = c1w + i * 16 + rq;
            int c2 = c2w + cj * 8 + cq;
            *reinterpret_cast<float2*>(&dst[c1 * 128 + c2])       = make_float2(acc[i][cj].x, acc[i][cj].y);
            *reinterpret_cast<float2*>(&dst[(c1 + 8) * 128 + c2]) = make_float2(acc[i][cj].z, acc[i][cj].w);
        }
}

// =====================================================================
// K5b: reduce 8 split-K partials -> X_pooled, A_pooled (out), G
// =====================================================================
__global__ void k5b_reduce(float* __restrict__ out) {
    int idx = blockIdx.x * blockDim.x + threadIdx.x;
    if (idx >= 3 * 8 * 16384) return;
    int p = idx / 131072;
    int rem = idx - p * 131072;
    int b = rem >> 14;
    int kc = rem & 16383;
    const float* s0 = g_part + ((size_t)(p * 8 + b) * 8) * 16384 + kc;
    float s = 0.f;
    #pragma unroll
    for (int ch = 0; ch < 8; ch++) s += s0[(size_t)ch * 16384];
    if (p == 0)      out[(size_t)b * 16384 + kc] = s;
    else if (p == 1) out[OUT_AP + (size_t)b * 16384 + kc] = s;
    else             g_G[b * 16384 + kc] = s;
}

// =====================================================================
// K6: losses. LP_b^2 = sumA_b - 2 tr(A_pooled_b) + ||G_b||_F^2
// =====================================================================
__global__ void k6_final(float* __restrict__ out) {
    int t = threadIdx.x;
    __shared__ float red[256];

    float lo = 0.f;
    for (int i = t; i < ROWS; i += 256) lo += g_entrRow[i];
    red[t] = lo; __syncthreads();
    for (int s2 = 128; s2 > 0; s2 >>= 1) {
        if (t < s2) red[t] += red[t + s2];
        __syncthreads();
    }
    float entr = red[0] / (float)ROWS;
    __syncthreads();

    float lpsum = 0.f;
    for (int b = 0; b < 8; b++) {
        float la = 0.f;
        for (int i = t; i < NN; i += 256) la += (float)g_nnz[b * NN + i];
        red[t] = la; __syncthreads();
        for (int s2 = 128; s2 > 0; s2 >>= 1) { if (t < s2) red[t] += red[t + s2]; __syncthreads(); }
        float sumA = red[0]; __syncthreads();

        float ltr = (t < 128) ? out[OUT_AP + (size_t)b * 16384 + t * 129] : 0.f;
        red[t] = ltr; __syncthreads();
        for (int s2 = 128; s2 > 0; s2 >>= 1) { if (t < s2) red[t] += red[t + s2]; __syncthreads(); }
        float tr = red[0]; __syncthreads();

        float lg = 0.f;
        for (int i = t; i < 16384; i += 256) { float v = g_G[b * 16384 + i]; lg += v * v; }
        red[t] = lg; __syncthreads();
        for (int s2 = 128; s2 > 0; s2 >>= 1) { if (t < s2) red[t] += red[t + s2]; __syncthreads(); }
        float gg = red[0]; __syncthreads();

        lpsum += sqrtf(fmaxf(sumA - 2.f * tr + gg, 0.f));
    }
    if (t == 0) {
        out[OUT_LP] = lpsum / 8.0f;
        out[OUT_ENT] = entr;
    }
}

// =====================================================================
extern "C" void kernel_launch(void* const* d_in, const int* in_sizes, int n_in,
                              void* d_out, int out_size) {
    const float* X  = (const float*)d_in[0];
    const float* A  = (const float*)d_in[1];
    const float* We = (const float*)d_in[2];
    const float* Wp = (const float*)d_in[3];
    float* out = (float*)d_out;

    cudaFuncSetAttribute(p1_logits, cudaFuncAttributeMaxDynamicSharedMemorySize, P1SMEM);
    cudaFuncSetAttribute(p2_TU, cudaFuncAttributeMaxDynamicSharedMemorySize, P2SMEM);
    cudaFuncSetAttribute(k5t_outer, cudaFuncAttributeMaxDynamicSharedMemorySize, K5SMEM);

    k1_scan<<<ROWS, 256>>>(A);
    k2_xw<<<ROWS / 32, 256>>>(X, We, Wp);
    dim3 gd(32, 8);
    p1_logits<<<gd, 256, P1SMEM>>>(out);
    p2_TU<<<gd, 256, P2SMEM>>>(out);
    dim3 g5(8, 8, 3);
    k5t_outer<<<g5, 256, K5SMEM>>>();
    k5b_reduce<<<(3 * 8 * 16384 + 255) / 256, 256>>>(out);
    k6_final<<<1, 256>>>(out);
}

// round 14
// speedup vs baseline: 1.3402x; 1.1554x over previous
#include <cuda_runtime.h>
#include <cuda_bf16.h>
#include <cstdint>

// DiffPool: B=8, N=2048, F=C=K=128.
// out: X_pooled[8,128,128] | A_pooled[8,128,128] | S[8,2048,128] | LP_loss | entr_loss
//
// A exactly binary -> exact bf16; HMMA mma.sync m16n8k16 fp32-acc.
//   K2T (tensor, 3-term hi/lo): [Xe | Yp] = X @ [We | Wp]
//   P1: logits = d*(A@Yp + Yp) -> fused softmax -> S fp32, Shi/Slo, dShi, entropy
//   P2: A@[Shi | dShi] (64x256 tile) -> Thi/Tlo, U=d*acc+d^2*S -> Uhi/Ulo
//   K5T (hi/lo, hh+hl+lh): X_pooled = U^T Xe, A_pooled = S^T T, G = S^T S
//   LP^2_b = sumA_b - 2 tr(A_pooled_b) + ||G_b||_F^2
// R13 confirmed: vectorized hi/lo epilogues. This round: tensorize k2 (was the
// last FFMA GEMM, est ~45us on the scalar pipe).

#define BB 8
#define NN 2048
#define ROWS (BB*NN)
#define OUT_AP 131072
#define OUT_S  262144
#define OUT_LP 2359296
#define OUT_ENT 2359297

// P1 buffer: A 64x64bf16 (stride 144B) = 9216 + B 64x128 (swz 256B) = 16384 -> 25600
#define P1BUF 25600
#define P1SMEM (2*P1BUF)
// P2 buffer: A 9216 + S 16384 + dS 16384 = 41984
#define P2BUF 41984
#define P2SMEM (2*P2BUF)
// K5T buffer: 4 arrays x (32 x 256B) = 32768; 3 buffers
#define K5BUF 32768
#define K5SMEM (3*K5BUF)
// K2T buffer: Xh/Xl 64x32bf16 (stride 80B) = 5120 each + 4 W arrays (32x256B) = 8192 each
#define K2BUF 43008
#define K2SMEM (2*K2BUF)

// ---- scratch ----
__device__ __nv_bfloat16 g_Abf[(size_t)ROWS*2048];
__device__ __nv_bfloat16 g_Xh[(size_t)ROWS*128];         // X hi/lo bf16
__device__ __nv_bfloat16 g_Xl[(size_t)ROWS*128];
__device__ __nv_bfloat16 g_Wh[128*256];                   // [We|Wp] hi/lo bf16
__device__ __nv_bfloat16 g_Wl[128*256];
__device__ float g_Yp[(size_t)ROWS*128];
__device__ __nv_bfloat16 g_Yphi[(size_t)ROWS*128];
__device__ __nv_bfloat16 g_Xehi[(size_t)ROWS*128];
__device__ __nv_bfloat16 g_Xelo[(size_t)ROWS*128];
__device__ __nv_bfloat16 g_Shi[(size_t)ROWS*128];
__device__ __nv_bfloat16 g_Slo[(size_t)ROWS*128];
__device__ __nv_bfloat16 g_dShi[(size_t)ROWS*128];
__device__ __nv_bfloat16 g_Thi[(size_t)ROWS*128];
__device__ __nv_bfloat16 g_Tlo[(size_t)ROWS*128];
__device__ __nv_bfloat16 g_Uhi[(size_t)ROWS*128];
__device__ __nv_bfloat16 g_Ulo[(size_t)ROWS*128];
__device__ float g_d[ROWS];
__device__ int   g_nnz[ROWS];
__device__ float g_entrRow[ROWS];
__device__ float g_part[(size_t)3*8*8*16384];
__device__ float g_G[8*128*128];

// ---------------- PTX helpers ----------------
__device__ __forceinline__ uint32_t smem_u32(const void* p) {
    uint32_t a;
    asm("{ .reg .u64 t; cvta.to.shared.u64 t, %1; cvt.u32.u64 %0, t; }" : "=r"(a) : "l"(p));
    return a;
}
__device__ __forceinline__ void cpa16(uint32_t s, const void* g) {
    asm volatile("cp.async.cg.shared.global [%0], [%1], 16;" :: "r"(s), "l"(g));
}
#define CPA_COMMIT() asm volatile("cp.async.commit_group;" ::: "memory")
#define CPA_WAIT1()  asm volatile("cp.async.wait_group 1;" ::: "memory")
#define CPA_WAIT0()  asm volatile("cp.async.wait_group 0;" ::: "memory")

__device__ __forceinline__ void ldsm4(uint32_t& r0, uint32_t& r1, uint32_t& r2, uint32_t& r3,
                                      uint32_t a) {
    asm volatile("ldmatrix.sync.aligned.m8n8.x4.shared.b16 {%0,%1,%2,%3}, [%4];"
                 : "=r"(r0), "=r"(r1), "=r"(r2), "=r"(r3) : "r"(a));
}
__device__ __forceinline__ void ldsm4t(uint32_t& r0, uint32_t& r1, uint32_t& r2, uint32_t& r3,
                                       uint32_t a) {
    asm volatile("ldmatrix.sync.aligned.m8n8.x4.trans.shared.b16 {%0,%1,%2,%3}, [%4];"
                 : "=r"(r0), "=r"(r1), "=r"(r2), "=r"(r3) : "r"(a));
}
__device__ __forceinline__ void mma_bf16(float4& d, const uint32_t* a, const uint32_t* b) {
    asm volatile("mma.sync.aligned.m16n8k16.row.col.f32.bf16.bf16.f32 "
                 "{%0,%1,%2,%3}, {%4,%5,%6,%7}, {%8,%9}, {%0,%1,%2,%3};"
                 : "+f"(d.x), "+f"(d.y), "+f"(d.z), "+f"(d.w)
                 : "r"(a[0]), "r"(a[1]), "r"(a[2]), "r"(a[3]), "r"(b[0]), "r"(b[1]));
}
__device__ __forceinline__ void store_hilo2(__nv_bfloat16* Hd, __nv_bfloat16* Ld,
                                            size_t base, float vx, float vy) {
    __nv_bfloat16 h0 = __float2bfloat16_rn(vx);
    __nv_bfloat16 h1 = __float2bfloat16_rn(vy);
    __nv_bfloat16 l0 = __float2bfloat16_rn(vx - __bfloat162float(h0));
    __nv_bfloat16 l1 = __float2bfloat16_rn(vy - __bfloat162float(h1));
    *reinterpret_cast<__nv_bfloat162*>(Hd + base) = __halves2bfloat162(h0, h1);
    *reinterpret_cast<__nv_bfloat162*>(Ld + base) = __halves2bfloat162(l0, l1);
}

// =====================================================================
// K1: row-sum of A + exact bf16 conversion
// =====================================================================
__global__ void k1_scan(const float* __restrict__ A) {
    int row = blockIdx.x;
    int t = threadIdx.x;
    const float4* ar = reinterpret_cast<const float4*>(A + (size_t)row * NN);
    __nv_bfloat16* dstb = g_Abf + (size_t)row * NN;
    int cnt = 0;
    #pragma unroll
    for (int i = 0; i < 2; i++) {
        int cg = t + (i << 8);
        float4 v = ar[cg];
        cnt += (v.x != 0.f) + (v.y != 0.f) + (v.z != 0.f) + (v.w != 0.f);
        __nv_bfloat162 p0 = __floats2bfloat162_rn(v.x, v.y);
        __nv_bfloat162 p1 = __floats2bfloat162_rn(v.z, v.w);
        *reinterpret_cast<__nv_bfloat162*>(dstb + (cg << 2))     = p0;
        *reinterpret_cast<__nv_bfloat162*>(dstb + (cg << 2) + 2) = p1;
    }
    int lane = t & 31, w = t >> 5;
    #pragma unroll
    for (int o = 16; o > 0; o >>= 1) cnt += __shfl_xor_sync(0xffffffffu, cnt, o);
    __shared__ int wtot[8];
    if (lane == 0) wtot[w] = cnt;
    __syncthreads();
    if (t == 0) {
        int s = 0;
        #pragma unroll
        for (int i = 0; i < 8; i++) s += wtot[i];
        g_nnz[row] = s;
        g_d[row] = rsqrtf((float)s + 1.0f);
    }
}

// =====================================================================
// K0: X -> hi/lo bf16
// =====================================================================
__global__ void k0_convX(const float* __restrict__ X) {
    size_t idx = (size_t)blockIdx.x * 256 + threadIdx.x;   // 0..524287 float4s
    float4 v = reinterpret_cast<const float4*>(X)[idx];
    size_t base = idx * 4;
    store_hilo2(g_Xh, g_Xl, base,     v.x, v.y);
    store_hilo2(g_Xh, g_Xl, base + 2, v.z, v.w);
}

// =====================================================================
// KW: [We | Wp] -> hi/lo bf16, layout [128][256]
// =====================================================================
__global__ void kW_conv(const float* __restrict__ We, const float* __restrict__ Wp) {
    int idx = blockIdx.x * 256 + threadIdx.x;              // 0..8191 float4 groups
    int k = idx >> 6, c4 = idx & 63;
    int c = c4 * 4;
    const float* src = (c < 128) ? (We + k * 128 + c) : (Wp + k * 128 + (c - 128));
    float4 v = *reinterpret_cast<const float4*>(src);
    size_t base = (size_t)k * 256 + c;
    store_hilo2(g_Wh, g_Wl, base,     v.x, v.y);
    store_hilo2(g_Wh, g_Wl, base + 2, v.z, v.w);
}

// =====================================================================
// K2T: [Xe | Yp] = X @ [We | Wp] via 3-term hi/lo HMMA.
// 64x256 CTA tile, grid 256, 256 thr (2x4 warps of 32x64), K-chunk 32,
// 4 chunks, 2-stage. Epilogue: Xe half -> Xehi/Xelo; Yp half -> d-scaled
// Yp fp32 + Yphi bf16.
// =====================================================================
__global__ void __launch_bounds__(256, 2)
k2t_xw() {
    extern __shared__ char smem[];
    uint32_t sb = smem_u32(smem);
    int tid = threadIdx.x;
    int wid = tid >> 5, lane = tid & 31;
    int n0 = blockIdx.x * 64;                      // global row tile
    const __nv_bfloat16* Xhg = g_Xh + (size_t)n0 * 128;
    const __nv_bfloat16* Xlg = g_Xl + (size_t)n0 * 128;

    float4 acc[2][8];
    #pragma unroll
    for (int i = 0; i < 2; i++)
        #pragma unroll
        for (int j = 0; j < 8; j++) acc[i][j] = make_float4(0.f, 0.f, 0.f, 0.f);

    int n0w = (wid >> 2) * 32;
    int cw = wid & 3;
    int c0l = (cw & 1) * 64;
    uint32_t bh_off = (cw >= 2) ? 26624u : 10240u;  // W hi array for this half
    int sel = lane >> 3, rr = lane & 7;

    auto stage = [&](int ch, int buf) {
        uint32_t s0 = sb + buf * K2BUF;
        int kc = ch * 32;
        #pragma unroll
        for (int q = 0; q < 2; q++) {              // Xh, Xl: 64 rows x 64B (stride 80)
            int idx = tid + q * 256;               // 0..511
            int which = idx >> 8, r = idx & 255;
            int row = r >> 2, u = r & 3;
            const __nv_bfloat16* src = which ? Xlg : Xhg;
            cpa16(s0 + which * 5120 + row * 80 + u * 16,
                  src + (size_t)row * 128 + kc + u * 8);
        }
        #pragma unroll
        for (int q = 0; q < 8; q++) {              // 4 W arrays: 32 rows x 256B swz
            int idx = tid + q * 256;               // 0..2047
            int arr = idx >> 9, r = idx & 511;
            int k = r >> 4, u = r & 15;
            uint32_t so = k * 256 + ((u * 16) ^ ((k & 7) << 4));
            const __nv_bfloat16* src = (arr & 1) ? g_Wl : g_Wh;
            int cb = (arr >= 2) ? 128 : 0;
            cpa16(s0 + 10240 + arr * 8192 + so,
                  src + (size_t)(kc + k) * 256 + cb + u * 8);
        }
        CPA_COMMIT();
    };

    stage(0, 0);
    for (int ch = 0; ch < 4; ch++) {
        if (ch < 3) { stage(ch + 1, (ch + 1) & 1); CPA_WAIT1(); }
        else CPA_WAIT0();
        __syncthreads();
        uint32_t s0 = sb + (ch & 1) * K2BUF;
        #pragma unroll
        for (int ks = 0; ks < 2; ks++) {
            uint32_t xh[2][4], xl[2][4];
            #pragma unroll
            for (int i = 0; i < 2; i++) {
                int row = n0w + i * 16 + (sel & 1) * 8 + rr;
                uint32_t ad = row * 80 + ks * 32 + (sel >> 1) * 16;
                ldsm4(xh[i][0], xh[i][1], xh[i][2], xh[i][3], s0 + ad);
                ldsm4(xl[i][0], xl[i][1], xl[i][2], xl[i][3], s0 + 5120 + ad);
            }
            #pragma unroll
            for (int cg = 0; cg < 4; cg++) {
                int krow = ks * 16 + (sel & 1) * 8 + rr;
                int colb = (c0l + cg * 16) * 2 + (sel >> 1) * 16;
                uint32_t ad = s0 + bh_off + krow * 256 + (colb ^ ((krow & 7) << 4));
                uint32_t bh2[2][2], bl2[2][2];
                ldsm4t(bh2[0][0], bh2[0][1], bh2[1][0], bh2[1][1], ad);
                ldsm4t(bl2[0][0], bl2[0][1], bl2[1][0], bl2[1][1], ad + 8192);
                #pragma unroll
                for (int i = 0; i < 2; i++)
                    #pragma unroll
                    for (int h = 0; h < 2; h++) {
                        int cj = cg * 2 + h;
                        mma_bf16(acc[i][cj], xh[i], bh2[h]);
                        mma_bf16(acc[i][cj], xh[i], bl2[h]);
                        mma_bf16(acc[i][cj], xl[i], bh2[h]);
                    }
            }
        }
        __syncthreads();
    }
    CPA_WAIT0();

    int rq = lane >> 2, cq = (lane & 3) * 2;
    bool isYp = (cw >= 2);
    #pragma unroll
    for (int i = 0; i < 2; i++)
        #pragma unroll
        for (int cj = 0; cj < 8; cj++) {
            int c = c0l + cj * 8 + cq;
            size_t nr0 = (size_t)n0 + n0w + i * 16 + rq;
            size_t nr1 = nr0 + 8;
            float v0x = acc[i][cj].x, v0y = acc[i][cj].y;
            float v1x = acc[i][cj].z, v1y = acc[i][cj].w;
            if (isYp) {
                float d0 = g_d[nr0], d1 = g_d[nr1];
                v0x *= d0; v0y *= d0; v1x *= d1; v1y *= d1;
                *reinterpret_cast<float2*>(&g_Yp[nr0 * 128 + c]) = make_float2(v0x, v0y);
                *reinterpret_cast<float2*>(&g_Yp[nr1 * 128 + c]) = make_float2(v1x, v1y);
                *reinterpret_cast<__nv_bfloat162*>(&g_Yphi[nr0 * 128 + c]) =
                    __floats2bfloat162_rn(v0x, v0y);
                *reinterpret_cast<__nv_bfloat162*>(&g_Yphi[nr1 * 128 + c]) =
                    __floats2bfloat162_rn(v1x, v1y);
            } else {
                store_hilo2(g_Xehi, g_Xelo, nr0 * 128 + c, v0x, v0y);
                store_hilo2(g_Xehi, g_Xelo, nr1 * 128 + c, v1x, v1y);
            }
        }
}

// =====================================================================
// P1: 64x128 tile of A@Yphi, fused softmax. grid (32,8), 256 thr,
// K-chunk 64, 2-stage, (256,2).
// =====================================================================
__global__ void __launch_bounds__(256, 2)
p1_logits(float* __restrict__ out) {
    extern __shared__ char smem[];
    uint32_t sb = smem_u32(smem);
    int tid = threadIdx.x;
    int wid = tid >> 5, lane = tid & 31;
    int n0 = blockIdx.x * 64, b = blockIdx.y;
    const __nv_bfloat16* Ag = g_Abf + ((size_t)b * 2048 + n0) * 2048;
    const __nv_bfloat16* Bg = g_Yphi + (size_t)b * 2048 * 128;

    float4 acc[2][4];
    #pragma unroll
    for (int i = 0; i < 2; i++)
        #pragma unroll
        for (int j = 0; j < 4; j++) acc[i][j] = make_float4(0.f, 0.f, 0.f, 0.f);

    int n0w = (wid >> 2) * 32, c0w = (wid & 3) * 32;
    int sel = lane >> 3, rr = lane & 7;

    auto stage = [&](int ch, int buf) {
        uint32_t s0 = sb + buf * P1BUF;
        int kc = ch * 64;
        #pragma unroll
        for (int q = 0; q < 2; q++) {
            int idx = tid + q * 256;
            int row = idx >> 3, u = idx & 7;
            cpa16(s0 + row * 144 + u * 16, Ag + (size_t)row * 2048 + kc + u * 8);
        }
        #pragma unroll
        for (int q = 0; q < 4; q++) {
            int idx = tid + q * 256;
            int k = idx >> 4, u = idx & 15;
            uint32_t so = k * 256 + ((u * 16) ^ ((k & 7) << 4));
            cpa16(s0 + 9216 + so, Bg + (size_t)(kc + k) * 128 + u * 8);
        }
        CPA_COMMIT();
    };

    stage(0, 0);
    for (int ch = 0; ch < 32; ch++) {
        if (ch < 31) { stage(ch + 1, (ch + 1) & 1); CPA_WAIT1(); }
        else CPA_WAIT0();
        __syncthreads();
        uint32_t s0 = sb + (ch & 1) * P1BUF;
        #pragma unroll
        for (int ks = 0; ks < 4; ks++) {
            uint32_t a[2][4];
            #pragma unroll
            for (int i = 0; i < 2; i++) {
                int row = n0w + i * 16 + (sel & 1) * 8 + rr;
                ldsm4(a[i][0], a[i][1], a[i][2], a[i][3],
                      s0 + row * 144 + ks * 32 + (sel >> 1) * 16);
            }
            uint32_t bh[4][2];
            #pragma unroll
            for (int cg = 0; cg < 2; cg++) {
                int krow = ks * 16 + (sel & 1) * 8 + rr;
                int colb = (c0w + cg * 16) * 2 + (sel >> 1) * 16;
                uint32_t ad = s0 + 9216 + krow * 256 + (colb ^ ((krow & 7) << 4));
                ldsm4t(bh[cg*2][0], bh[cg*2][1], bh[cg*2+1][0], bh[cg*2+1][1], ad);
            }
            #pragma unroll
            for (int i = 0; i < 2; i++)
                #pragma unroll
                for (int cj = 0; cj < 4; cj++)
                    mma_bf16(acc[i][cj], a[i], bh[cj]);
        }
        __syncthreads();
    }
    CPA_WAIT0();
    __syncthreads();

    float* smlog = reinterpret_cast<float*>(smem);    // [64][132] = 33792B
    int rq = lane >> 2, cq = (lane & 3) * 2;
    #pragma unroll
    for (int i = 0; i < 2; i++)
        #pragma unroll
        for (int cj = 0; cj < 4; cj++) {
            int rowl = n0w + i * 16 + rq;
            int col = c0w + cj * 8 + cq;
            *reinterpret_cast<float2*>(&smlog[rowl * 132 + col])       = make_float2(acc[i][cj].x, acc[i][cj].y);
            *reinterpret_cast<float2*>(&smlog[(rowl + 8) * 132 + col]) = make_float2(acc[i][cj].z, acc[i][cj].w);
        }
    __syncthreads();

    #pragma unroll
    for (int r = 0; r < 8; r++) {
        int rowl = wid * 8 + r;
        size_t nr = (size_t)b * 2048 + n0 + rowl;
        float dn = g_d[nr];
        float4 Lc = *reinterpret_cast<float4*>(&smlog[rowl * 132 + lane * 4]);
        float4 Yv = reinterpret_cast<const float4*>(g_Yp + nr * 128)[lane];
        float l0 = dn * (Lc.x + Yv.x), l1 = dn * (Lc.y + Yv.y);
        float l2 = dn * (Lc.z + Yv.z), l3 = dn * (Lc.w + Yv.w);
        float m = fmaxf(fmaxf(l0, l1), fmaxf(l2, l3));
        #pragma unroll
        for (int o = 16; o > 0; o >>= 1) m = fmaxf(m, __shfl_xor_sync(0xffffffffu, m, o));
        float e0 = expf(l0 - m), e1 = expf(l1 - m), e2 = expf(l2 - m), e3 = expf(l3 - m);
        float ss = (e0 + e1) + (e2 + e3);
        #pragma unroll
        for (int o = 16; o > 0; o >>= 1) ss += __shfl_xor_sync(0xffffffffu, ss, o);
        float inv = 1.f / ss;
        float s0v = e0 * inv, s1v = e1 * inv, s2v = e2 * inv, s3v = e3 * inv;
        reinterpret_cast<float4*>(out + OUT_S + nr * 128)[lane] = make_float4(s0v, s1v, s2v, s3v);
        store_hilo2(g_Shi, g_Slo, nr * 128 + lane * 4,     s0v, s1v);
        store_hilo2(g_Shi, g_Slo, nr * 128 + lane * 4 + 2, s2v, s3v);
        __nv_bfloat162 dh0 = __floats2bfloat162_rn(dn * s0v, dn * s1v);
        __nv_bfloat162 dh1 = __floats2bfloat162_rn(dn * s2v, dn * s3v);
        *reinterpret_cast<__nv_bfloat162*>(g_dShi + nr * 128 + lane * 4)     = dh0;
        *reinterpret_cast<__nv_bfloat162*>(g_dShi + nr * 128 + lane * 4 + 2) = dh1;
        float ent = -(s0v * logf(s0v + 1e-7f) + s1v * logf(s1v + 1e-7f)
                    + s2v * logf(s2v + 1e-7f) + s3v * logf(s3v + 1e-7f));
        #pragma unroll
        for (int o = 16; o > 0; o >>= 1) ent += __shfl_xor_sync(0xffffffffu, ent, o);
        if (lane == 0) g_entrRow[nr] = ent;
    }
}

// =====================================================================
// P2: 64x256 tile of A@[Shi | dShi] -> Thi/Tlo, Uhi/Ulo (vectorized).
// grid (32,8), 256 thr, K-chunk 64, 2-stage, (256,2).
// =====================================================================
__global__ void __launch_bounds__(256, 2)
p2_TU(const float* __restrict__ out) {
    extern __shared__ char smem[];
    uint32_t sb = smem_u32(smem);
    int tid = threadIdx.x;
    int wid = tid >> 5, lane = tid & 31;
    int n0 = blockIdx.x * 64, b = blockIdx.y;
    const __nv_bfloat16* Ag = g_Abf + ((size_t)b * 2048 + n0) * 2048;
    const __nv_bfloat16* Sg = g_Shi + (size_t)b * 2048 * 128;
    const __nv_bfloat16* Dg = g_dShi + (size_t)b * 2048 * 128;

    float4 acc[2][8];
    #pragma unroll
    for (int i = 0; i < 2; i++)
        #pragma unroll
        for (int j = 0; j < 8; j++) acc[i][j] = make_float4(0.f, 0.f, 0.f, 0.f);

    int n0w = (wid >> 2) * 32;
    int cw = wid & 3;
    int c0l = (cw & 1) * 64;
    uint32_t bbase_off = 9216 + (cw >= 2 ? 16384u : 0u);
    int sel = lane >> 3, rr = lane & 7;

    auto stage = [&](int ch, int buf) {
        uint32_t s0 = sb + buf * P2BUF;
        int kc = ch * 64;
        #pragma unroll
        for (int q = 0; q < 2; q++) {
            int idx = tid + q * 256;
            int row = idx >> 3, u = idx & 7;
            cpa16(s0 + row * 144 + u * 16, Ag + (size_t)row * 2048 + kc + u * 8);
        }
        #pragma unroll
        for (int q = 0; q < 8; q++) {
            int idx = tid + q * 256;
            int blk = idx >> 10, r = idx & 1023;
            int k = r >> 4, u = r & 15;
            uint32_t so = k * 256 + ((u * 16) ^ ((k & 7) << 4));
            const __nv_bfloat16* src = blk ? Dg : Sg;
            cpa16(s0 + 9216 + blk * 16384 + so, src + (size_t)(kc + k) * 128 + u * 8);
        }
        CPA_COMMIT();
    };

    stage(0, 0);
    for (int ch = 0; ch < 32; ch++) {
        if (ch < 31) { stage(ch + 1, (ch + 1) & 1); CPA_WAIT1(); }
        else CPA_WAIT0();
        __syncthreads();
        uint32_t s0 = sb + (ch & 1) * P2BUF;
        #pragma unroll
        for (int ks = 0; ks < 4; ks++) {
            uint32_t a[2][4];
            #pragma unroll
            for (int i = 0; i < 2; i++) {
                int row = n0w + i * 16 + (sel & 1) * 8 + rr;
                ldsm4(a[i][0], a[i][1], a[i][2], a[i][3],
                      s0 + row * 144 + ks * 32 + (sel >> 1) * 16);
            }
            uint32_t bh[8][2];
            #pragma unroll
            for (int cg = 0; cg < 4; cg++) {
                int krow = ks * 16 + (sel & 1) * 8 + rr;
                int colb = (c0l + cg * 16) * 2 + (sel >> 1) * 16;
                uint32_t ad = s0 + bbase_off + krow * 256 + (colb ^ ((krow & 7) << 4));
                ldsm4t(bh[cg*2][0], bh[cg*2][1], bh[cg*2+1][0], bh[cg*2+1][1], ad);
            }
            #pragma unroll
            for (int i = 0; i < 2; i++)
                #pragma unroll
                for (int cj = 0; cj < 8; cj++)
                    mma_bf16(acc[i][cj], a[i], bh[cj]);
        }
        __syncthreads();
    }
    CPA_WAIT0();

    int rq = lane >> 2, cq = (lane & 3) * 2;
    bool isU = (cw >= 2);
    __nv_bfloat16* Hd = isU ? g_Uhi : g_Thi;
    __nv_bfloat16* Ld = isU ? g_Ulo : g_Tlo;
    #pragma unroll
    for (int i = 0; i < 2; i++)
        #pragma unroll
        for (int cj = 0; cj < 8; cj++) {
            int n = n0 + n0w + i * 16 + rq;
            int c = c0l + cj * 8 + cq;
            size_t nr0 = (size_t)b * 2048 + n;
            size_t nr1 = nr0 + 8;
            float v0x = acc[i][cj].x, v0y = acc[i][cj].y;
            float v1x = acc[i][cj].z, v1y = acc[i][cj].w;
            if (isU) {
                float d0 = g_d[nr0], d1 = g_d[nr1];
                float2 sv0 = *reinterpret_cast<const float2*>(&out[OUT_S + nr0 * 128 + c]);
                float2 sv1 = *reinterpret_cast<const float2*>(&out[OUT_S + nr1 * 128 + c]);
                v0x = d0 * v0x + d0 * d0 * sv0.x;
                v0y = d0 * v0y + d0 * d0 * sv0.y;
                v1x = d1 * v1x + d1 * d1 * sv1.x;
                v1y = d1 * v1y + d1 * d1 * sv1.y;
            }
            store_hilo2(Hd, Ld, nr0 * 128 + c, v0x, v0y);
            store_hilo2(Hd, Ld, nr1 * 128 + c, v1x, v1y);
        }
}

// =====================================================================
// K5T: tensorized L^T R, hi/lo (hh+hl+lh). Split-K over n; 3 bufs,
// 2 in flight, drain-aware tail. grid (8,8,3), 256 thr.
// =====================================================================
__global__ void __launch_bounds__(256, 2)
k5t_outer() {
    extern __shared__ char smem[];
    uint32_t sb = smem_u32(smem);
    int tid = threadIdx.x;
    int wid = tid >> 5, lane = tid & 31;
    int split = blockIdx.x, b = blockIdx.y, p = blockIdx.z;
    size_t boff = (size_t)b * 2048 * 128;

    const __nv_bfloat16* src[4];
    if (p == 0)      { src[0] = g_Uhi; src[1] = g_Ulo; src[2] = g_Xehi; src[3] = g_Xelo; }
    else if (p == 1) { src[0] = g_Shi; src[1] = g_Slo; src[2] = g_Thi;  src[3] = g_Tlo; }
    else             { src[0] = g_Shi; src[1] = g_Slo; src[2] = g_Shi;  src[3] = g_Slo; }

    float4 acc[2][8];
    #pragma unroll
    for (int i = 0; i < 2; i++)
        #pragma unroll
        for (int j = 0; j < 8; j++) acc[i][j] = make_float4(0.f, 0.f, 0.f, 0.f);

    int c1w = (wid >> 1) * 32, c2w = (wid & 1) * 64;
    int sel = lane >> 3, rr = lane & 7;

    auto stage = [&](int ch) {
        uint32_t s0 = sb + (ch % 3) * K5BUF;
        int nc = split * 256 + ch * 32;
        #pragma unroll
        for (int q = 0; q < 8; q++) {
            int arr = q >> 1;
            int r = ((q & 1) << 8) + tid;
            int k = r >> 4, u = r & 15;
            uint32_t so = k * 256 + ((u * 16) ^ ((k & 7) << 4));
            cpa16(s0 + arr * 8192 + so, src[arr] + boff + (size_t)(nc + k) * 128 + u * 8);
        }
        CPA_COMMIT();
    };

    stage(0); stage(1);
    for (int ch = 0; ch < 8; ch++) {
        if (ch < 7) CPA_WAIT1();
        else CPA_WAIT0();
        __syncthreads();
        uint32_t s0 = sb + (ch % 3) * K5BUF;
        #pragma unroll
        for (int ks = 0; ks < 2; ks++) {
            uint32_t lh[2][4], ll[2][4];
            #pragma unroll
            for (int i = 0; i < 2; i++) {
                int krow = ks * 16 + (sel >> 1) * 8 + rr;
                int colb = (c1w + i * 16 + (sel & 1) * 8) * 2;
                uint32_t ad = krow * 256 + (colb ^ ((krow & 7) << 4));
                ldsm4t(lh[i][0], lh[i][1], lh[i][2], lh[i][3], s0 + ad);
                ldsm4t(ll[i][0], ll[i][1], ll[i][2], ll[i][3], s0 + 8192 + ad);
            }
            #pragma unroll
            for (int cg = 0; cg < 4; cg++) {
                int krow = ks * 16 + (sel & 1) * 8 + rr;
                int colb = (c2w + cg * 16) * 2 + (sel >> 1) * 16;
                uint32_t ad = krow * 256 + (colb ^ ((krow & 7) << 4));
                uint32_t rh[2][2], rl[2][2];
                ldsm4t(rh[0][0], rh[0][1], rh[1][0], rh[1][1], s0 + 16384 + ad);
                ldsm4t(rl[0][0], rl[0][1], rl[1][0], rl[1][1], s0 + 24576 + ad);
                #pragma unroll
                for (int i = 0; i < 2; i++)
                    #pragma unroll
                    for (int h = 0; h < 2; h++) {
                        int cj = cg * 2 + h;
                        mma_bf16(acc[i][cj], lh[i], rh[h]);
                        mma_bf16(acc[i][cj], lh[i], rl[h]);
                        mma_bf16(acc[i][cj], ll[i], rh[h]);
                    }
            }
        }
        if (ch + 2 < 8) stage(ch + 2);
    }
    CPA_WAIT0();

    float* dst = g_part + ((size_t)((p * 8 + b) * 8 + split)) * 16384;
    int rq = lane >> 2, cq = (lane & 3) * 2;
    #pragma unroll
    for (int i = 0; i < 2; i++)
        #pragma unroll
        for (int cj = 0; cj < 8; cj++) {
            int c1 = c1w + i * 16 + rq;
            int c2 = c2w + cj * 8 + cq;
            *reinterpret_cast<float2*>(&dst[c1 * 128 + c2])       = make_float2(acc[i][cj].x, acc[i][cj].y);
            *reinterpret_cast<float2*>(&dst[(c1 + 8) * 128 + c2]) = make_float2(acc[i][cj].z, acc[i][cj].w);
        }
}

// =====================================================================
// K5b: reduce 8 split-K partials -> X_pooled, A_pooled (out), G
// =====================================================================
__global__ void k5b_reduce(float* __restrict__ out) {
    int idx = blockIdx.x * blockDim.x + threadIdx.x;
    if (idx >= 3 * 8 * 16384) return;
    int p = idx / 131072;
    int rem = idx - p * 131072;
    int b = rem >> 14;
    int kc = rem & 16383;
    const float* s0 = g_part + ((size_t)(p * 8 + b) * 8) * 16384 + kc;
    float s = 0.f;
    #pragma unroll
    for (int ch = 0; ch < 8; ch++) s += s0[(size_t)ch * 16384];
    if (p == 0)      out[(size_t)b * 16384 + kc] = s;
    else if (p == 1) out[OUT_AP + (size_t)b * 16384 + kc] = s;
    else             g_G[b * 16384 + kc] = s;
}

// =====================================================================
// K6: losses. LP_b^2 = sumA_b - 2 tr(A_pooled_b) + ||G_b||_F^2
// =====================================================================
__global__ void k6_final(float* __restrict__ out) {
    int t = threadIdx.x;
    __shared__ float red[256];

    float lo = 0.f;
    for (int i = t; i < ROWS; i += 256) lo += g_entrRow[i];
    red[t] = lo; __syncthreads();
    for (int s2 = 128; s2 > 0; s2 >>= 1) {
        if (t < s2) red[t] += red[t + s2];
        __syncthreads();
    }
    float entr = red[0] / (float)ROWS;
    __syncthreads();

    float lpsum = 0.f;
    for (int b = 0; b < 8; b++) {
        float la = 0.f;
        for (int i = t; i < NN; i += 256) la += (float)g_nnz[b * NN + i];
        red[t] = la; __syncthreads();
        for (int s2 = 128; s2 > 0; s2 >>= 1) { if (t < s2) red[t] += red[t + s2]; __syncthreads(); }
        float sumA = red[0]; __syncthreads();

        float ltr = (t < 128) ? out[OUT_AP + (size_t)b * 16384 + t * 129] : 0.f;
        red[t] = ltr; __syncthreads();
        for (int s2 = 128; s2 > 0; s2 >>= 1) { if (t < s2) red[t] += red[t + s2]; __syncthreads(); }
        float tr = red[0]; __syncthreads();

        float lg = 0.f;
        for (int i = t; i < 16384; i += 256) { float v = g_G[b * 16384 + i]; lg += v * v; }
        red[t] = lg; __syncthreads();
        for (int s2 = 128; s2 > 0; s2 >>= 1) { if (t < s2) red[t] += red[t + s2]; __syncthreads(); }
        float gg = red[0]; __syncthreads();

        lpsum += sqrtf(fmaxf(sumA - 2.f * tr + gg, 0.f));
    }
    if (t == 0) {
        out[OUT_LP] = lpsum / 8.0f;
        out[OUT_ENT] = entr;
    }
}

// =====================================================================
extern "C" void kernel_launch(void* const* d_in, const int* in_sizes, int n_in,
                              void* d_out, int out_size) {
    const float* X  = (const float*)d_in[0];
    const float* A  = (const float*)d_in[1];
    const float* We = (const float*)d_in[2];
    const float* Wp = (const float*)d_in[3];
    float* out = (float*)d_out;

    cudaFuncSetAttribute(k2t_xw, cudaFuncAttributeMaxDynamicSharedMemorySize, K2SMEM);
    cudaFuncSetAttribute(p1_logits, cudaFuncAttributeMaxDynamicSharedMemorySize, P1SMEM);
    cudaFuncSetAttribute(p2_TU, cudaFuncAttributeMaxDynamicSharedMemorySize, P2SMEM);
    cudaFuncSetAttribute(k5t_outer, cudaFuncAttributeMaxDynamicSharedMemorySize, K5SMEM);

    k1_scan<<<ROWS, 256>>>(A);
    k0_convX<<<2048, 256>>>(X);
    kW_conv<<<32, 256>>>(We, Wp);
    k2t_xw<<<256, 256, K2SMEM>>>();
    dim3 gd(32, 8);
    p1_logits<<<gd, 256, P1SMEM>>>(out);
    p2_TU<<<gd, 256, P2SMEM>>>(out);
    dim3 g5(8, 8, 3);
    k5t_outer<<<g5, 256, K5SMEM>>>();
    k5b_reduce<<<(3 * 8 * 16384 + 255) / 256, 256>>>(out);
    k6_final<<<1, 256>>>(out);
}